// round 3
// baseline (speedup 1.0000x reference)
#include <cuda_runtime.h>
#include <cuda_fp16.h>
#include <cstdint>

#define NS 48
#define BDIM 32768
#define KDIM 1536
#define KT 24              // K chunks of 64
#define STAGES 3
#define BM 128
#define BN 256
#define A_STG 16384        // 128 rows x 128B
#define B_STG 32768        // 256 rows x 128B
#define STAGE_BYTES (A_STG + B_STG)          // 49152
#define GEMM_SMEM (STAGES * STAGE_BYTES)     // 147456

// ---------------- device-global scratch (no runtime allocation allowed) ----
__device__ __half g_x16[(size_t)BDIM * KDIM];   // x in fp16
__device__ __half g_W[(size_t)KDIM * KDIM];     // fused operator [N=1536][K=1536], K contiguous
__device__ float  g_fwd[NS * NS];               // [s][o]
__device__ float  g_U[NS * NS * NS];            // [s][t][o2]
__device__ float  g_kh[32 * 32 * NS];           // [f*32+c][o2]
__device__ float  g_biasx[KDIM];                // bias broadcast over t

// ---------------- PTX helpers ---------------------------------------------
__device__ __forceinline__ unsigned s2u(const void* p) {
    return (unsigned)__cvta_generic_to_shared(p);
}
__device__ __forceinline__ void cpa16(unsigned s, const void* g) {
    asm volatile("cp.async.cg.shared.global [%0], [%1], 16;" :: "r"(s), "l"(g));
}
#define CPA_COMMIT asm volatile("cp.async.commit_group;" ::: "memory")
#define CPA_WAIT2  asm volatile("cp.async.wait_group 2;" ::: "memory")

__device__ __forceinline__ void ldsm4(unsigned* r, unsigned addr) {
    asm volatile("ldmatrix.sync.aligned.m8n8.x4.shared.b16 {%0,%1,%2,%3}, [%4];"
                 : "=r"(r[0]), "=r"(r[1]), "=r"(r[2]), "=r"(r[3]) : "r"(addr));
}
__device__ __forceinline__ void mma16816(float* d, const unsigned* a,
                                         unsigned b0, unsigned b1) {
    asm volatile(
        "mma.sync.aligned.m16n8k16.row.col.f32.f16.f16.f32 "
        "{%0,%1,%2,%3}, {%4,%5,%6,%7}, {%8,%9}, {%0,%1,%2,%3};"
        : "+f"(d[0]), "+f"(d[1]), "+f"(d[2]), "+f"(d[3])
        : "r"(a[0]), "r"(a[1]), "r"(a[2]), "r"(a[3]), "r"(b0), "r"(b1));
}

// ---------------- precompute -----------------------------------------------
// column o -> (d, block base, first idx, second idx), o = base + a*d + b
__device__ __forceinline__ void decode_o(int o, int& d, int& base, int& a, int& b) {
    if (o < 4)       { d = 1; base = o; a = 0; b = 0; }
    else if (o < 12) { int rem = o - 4;  d = 2; base = 4 + (rem >> 2) * 4; rem &= 3;  a = rem >> 1; b = rem & 1; }
    else             { int rem = o - 12; d = 3; base = 12 + (rem / 9) * 9; rem %= 9; a = rem / 3;  b = rem % 3; }
}

__global__ void k_pre1(const float* __restrict__ d1, const float* __restrict__ d2,
                       const float* __restrict__ d3, const float* __restrict__ bias) {
    for (int idx = threadIdx.x; idx < NS * NS; idx += blockDim.x) {
        int s = idx / NS, o = idx % NS;
        float v;
        if (o < 4)       v = d1[o * NS + s];
        else if (o < 12) { int rem = o - 4;  v = d2[((rem >> 2) * NS + s) * 4 + (rem & 3)]; }
        else             { int rem = o - 12; v = d3[((rem / 9) * NS + s) * 9 + (rem % 9)]; }
        g_fwd[s * NS + o] = v;
    }
    for (int j = threadIdx.x; j < KDIM; j += blockDim.x)
        g_biasx[j] = bias[j / NS];
}

__global__ void k_pre2() {  // U[s][t][(n,r,q)] = (d/48) sum_p fwd[s,(n,p,r)] fwd[t,(n,p,q)]
    __shared__ float sf[NS * NS];
    for (int i = threadIdx.x; i < NS * NS; i += blockDim.x) sf[i] = g_fwd[i];
    __syncthreads();
    int s = blockIdx.x;
    for (int e = threadIdx.x; e < NS * NS; e += blockDim.x) {
        int t = e / NS, o2 = e % NS;
        int d, base, r, q;
        decode_o(o2, d, base, r, q);
        float acc = 0.f;
        for (int p = 0; p < d; p++)
            acc += sf[s * NS + base + p * d + r] * sf[t * NS + base + p * d + q];
        g_U[(s * NS + t) * NS + o2] = acc * (float)d * (1.0f / 48.0f);
    }
}

__global__ void k_pre3(const float* __restrict__ kern) {  // kh[fc][o] = sum_s kern[fc,s] fwd[s,o]
    int fc = blockIdx.x;
    __shared__ float kr[NS];
    if (threadIdx.x < NS) kr[threadIdx.x] = kern[fc * NS + threadIdx.x];
    __syncthreads();
    if (threadIdx.x < NS) {
        float acc = 0.f;
        for (int s = 0; s < NS; s++) acc += kr[s] * g_fwd[s * NS + threadIdx.x];
        g_kh[fc * NS + threadIdx.x] = acc;
    }
}

__global__ void k_pre4() {  // W[f*48+t][c*48+s] = sum_o2 kh[f,c,o2] U[s,t,o2]
    int s = blockIdx.x, f = blockIdx.y;
    __shared__ float Us[NS * NS];
    __shared__ float khf[32 * NS];
    for (int i = threadIdx.x; i < NS * NS; i += blockDim.x) Us[i] = g_U[s * NS * NS + i];
    for (int i = threadIdx.x; i < 32 * NS; i += blockDim.x) khf[i] = g_kh[(f * 32) * NS + i];
    __syncthreads();
    for (int e = threadIdx.x; e < 32 * NS; e += blockDim.x) {
        int t = e >> 5, c = e & 31;
        float acc = 0.f;
#pragma unroll
        for (int o2 = 0; o2 < NS; o2++) acc += khf[c * NS + o2] * Us[t * NS + o2];
        g_W[(size_t)(f * NS + t) * KDIM + c * NS + s] = __float2half_rn(acc);
    }
}

__global__ void k_cvt(const float4* __restrict__ x) {
    size_t n4 = (size_t)BDIM * KDIM / 4;
    __half2* o = (__half2*)g_x16;
    for (size_t i = (size_t)blockIdx.x * blockDim.x + threadIdx.x; i < n4;
         i += (size_t)gridDim.x * blockDim.x) {
        float4 v = x[i];
        o[2 * i]     = __floats2half2_rn(v.x, v.y);
        o[2 * i + 1] = __floats2half2_rn(v.z, v.w);
    }
}

// ---------------- main GEMM ------------------------------------------------
// 128x256 CTA tile, 8 warps (2x4) each 64x64, K staged 64 at a time, 3 stages.
__device__ __forceinline__ void issue_stage(int kt, int tid, unsigned sb,
                                            const __half* gx, const __half* gw) {
    unsigned sa = sb + (unsigned)(kt % STAGES) * STAGE_BYTES;
    const __half* ga = gx + kt * 64;
    const __half* gb = gw + kt * 64;
#pragma unroll
    for (int it = 0; it < 12; it++) {
        int j = tid + it * 256;                 // 0..3071 16B-chunks
        bool isB = j >= 1024;
        int j2 = isB ? j - 1024 : j;
        int r = j2 >> 3, c = j2 & 7;            // row, 16B chunk within 128B row
        unsigned soff = (isB ? (unsigned)A_STG : 0u) + (unsigned)r * 128u
                      + (unsigned)((c ^ (r & 7)) << 4);
        const __half* g = (isB ? gb : ga) + (size_t)r * KDIM + c * 8;
        cpa16(sa + soff, g);
    }
}

__global__ void __launch_bounds__(256, 1) k_gemm(float* __restrict__ out) {
    extern __shared__ char smem[];
    unsigned sb = s2u(smem);
    int tid = threadIdx.x, lane = tid & 31, wid = tid >> 5;
    int wm = wid & 1, wn = wid >> 1;
    int n0 = blockIdx.x * BN, m0 = blockIdx.y * BM;

    const __half* gx = g_x16 + (size_t)m0 * KDIM;
    const __half* gw = g_W   + (size_t)n0 * KDIM;

    float acc[4][8][4];
#pragma unroll
    for (int i = 0; i < 4; i++)
#pragma unroll
        for (int j = 0; j < 8; j++)
#pragma unroll
            for (int e = 0; e < 4; e++) acc[i][j][e] = 0.f;

    // lane constants for ldmatrix addressing
    unsigned rowA = lane & 15;                  // A: lanes 0-15 rows, 16-31 same rows hi-k
    unsigned hkA  = lane >> 4;                  // A chunk select (k lo/hi 8)
    unsigned rowB = (lane & 7) | ((lane & 16) >> 1);   // B: 0-7,0-7,8-15,8-15
    unsigned ckB  = (lane >> 3) & 1;            // B chunk select pattern 0,1,0,1
    unsigned xorA = (lane & 7) << 4;            // (row&7)<<4 for both A and B

    issue_stage(0, tid, sb, gx, gw); CPA_COMMIT;
    issue_stage(1, tid, sb, gx, gw); CPA_COMMIT;

    for (int kt = 0; kt < KT; kt++) {
        if (kt + 2 < KT) issue_stage(kt + 2, tid, sb, gx, gw);
        CPA_COMMIT;
        CPA_WAIT2;
        __syncthreads();
        unsigned stg   = sb + (unsigned)(kt % STAGES) * STAGE_BYTES;
        unsigned baseA = stg + (unsigned)wm * (64 * 128) + rowA * 128;
        unsigned baseB = stg + A_STG + (unsigned)wn * (64 * 128) + rowB * 128;
#pragma unroll
        for (int s4 = 0; s4 < 4; s4++) {        // 4 k16-steps per 64-chunk
            unsigned a[4][4], b[4][4];
            unsigned chA = (((2 * s4 + hkA) << 4) ^ xorA);
            unsigned chB = (((2 * s4 + ckB) << 4) ^ xorA);
#pragma unroll
            for (int mi = 0; mi < 4; mi++) ldsm4(a[mi], baseA + mi * 2048 + chA);
#pragma unroll
            for (int nj = 0; nj < 4; nj++) ldsm4(b[nj], baseB + nj * 2048 + chB);
#pragma unroll
            for (int mi = 0; mi < 4; mi++)
#pragma unroll
                for (int nj = 0; nj < 8; nj++)
                    mma16816(acc[mi][nj], a[mi],
                             b[nj >> 1][(nj & 1) * 2], b[nj >> 1][(nj & 1) * 2 + 1]);
        }
        __syncthreads();
    }

    // ---- epilogue: direct coalesced-sector float2 stores + bias ----
    int rbase = m0 + wm * 64 + (lane >> 2);
    int cbase = n0 + wn * 64 + 2 * (lane & 3);
#pragma unroll
    for (int nj = 0; nj < 8; nj++) {
        int col = cbase + nj * 8;
        float b0 = g_biasx[col], b1 = g_biasx[col + 1];
#pragma unroll
        for (int mi = 0; mi < 4; mi++) {
            int r0 = rbase + mi * 16;
            float2 v0 = make_float2(acc[mi][nj][0] + b0, acc[mi][nj][1] + b1);
            float2 v1 = make_float2(acc[mi][nj][2] + b0, acc[mi][nj][3] + b1);
            *(float2*)&out[(size_t)r0 * KDIM + col] = v0;
            *(float2*)&out[(size_t)(r0 + 8) * KDIM + col] = v1;
        }
    }
}

// ---------------- launch ----------------------------------------------------
extern "C" void kernel_launch(void* const* d_in, const int* in_sizes, int n_in,
                              void* d_out, int out_size) {
    const float* x    = (const float*)d_in[0];
    const float* kern = (const float*)d_in[1];
    const float* bias = (const float*)d_in[2];
    const float* d1   = (const float*)d_in[3];
    const float* d2   = (const float*)d_in[4];
    const float* d3   = (const float*)d_in[5];
    float* out = (float*)d_out;

    k_pre1<<<1, 256>>>(d1, d2, d3, bias);
    k_pre2<<<48, 256>>>();
    k_pre3<<<1024, 64>>>(kern);
    k_pre4<<<dim3(48, 32), 256>>>();
    k_cvt<<<4096, 256>>>((const float4*)x);

    cudaFuncSetAttribute(k_gemm, cudaFuncAttributeMaxDynamicSharedMemorySize, GEMM_SMEM);
    k_gemm<<<dim3(KDIM / BN, BDIM / BM), 256, GEMM_SMEM>>>(out);
}

// round 4
// speedup vs baseline: 1.0823x; 1.0823x over previous
#include <cuda_runtime.h>
#include <cuda_fp16.h>
#include <cstdint>

#define NS 48
#define BDIM 32768
#define KDIM 1536
#define KT 24              // K chunks of 64
#define STAGES 3
#define BM 128
#define BN 256
#define A_STG 16384        // 128 rows x 128B (fp16)
#define B_STG 32768        // 256 rows x 128B (fp16)
#define STAGE_BYTES (A_STG + B_STG)          // 49152
#define GEMM_SMEM (STAGES * STAGE_BYTES)     // 147456

// ---------------- device-global scratch (no runtime allocation allowed) ----
__device__ __half g_W[(size_t)KDIM * KDIM];     // fused operator [N=1536][K=1536], K contiguous
__device__ float  g_fwd[NS * NS];               // [s][o]
__device__ float  g_U[NS * NS * NS];            // [s][t][o2]
__device__ float  g_kh[32 * 32 * NS];           // [f*32+c][o2]
__device__ float  g_biasx[KDIM];                // bias broadcast over t

// ---------------- PTX helpers ---------------------------------------------
__device__ __forceinline__ unsigned s2u(const void* p) {
    return (unsigned)__cvta_generic_to_shared(p);
}
__device__ __forceinline__ void cpa16(unsigned s, const void* g) {
    asm volatile("cp.async.cg.shared.global [%0], [%1], 16;" :: "r"(s), "l"(g));
}
#define CPA_COMMIT asm volatile("cp.async.commit_group;" ::: "memory")
#define CPA_WAIT2  asm volatile("cp.async.wait_group 2;" ::: "memory")

__device__ __forceinline__ void ldsm4(unsigned* r, unsigned addr) {
    asm volatile("ldmatrix.sync.aligned.m8n8.x4.shared.b16 {%0,%1,%2,%3}, [%4];"
                 : "=r"(r[0]), "=r"(r[1]), "=r"(r[2]), "=r"(r[3]) : "r"(addr));
}
__device__ __forceinline__ void mma16816(float* d, const unsigned* a,
                                         unsigned b0, unsigned b1) {
    asm volatile(
        "mma.sync.aligned.m16n8k16.row.col.f32.f16.f16.f32 "
        "{%0,%1,%2,%3}, {%4,%5,%6,%7}, {%8,%9}, {%0,%1,%2,%3};"
        : "+f"(d[0]), "+f"(d[1]), "+f"(d[2]), "+f"(d[3])
        : "r"(a[0]), "r"(a[1]), "r"(a[2]), "r"(a[3]), "r"(b0), "r"(b1));
}

// ---------------- precompute -----------------------------------------------
__device__ __forceinline__ void decode_o(int o, int& d, int& base, int& a, int& b) {
    if (o < 4)       { d = 1; base = o; a = 0; b = 0; }
    else if (o < 12) { int rem = o - 4;  d = 2; base = 4 + (rem >> 2) * 4; rem &= 3;  a = rem >> 1; b = rem & 1; }
    else             { int rem = o - 12; d = 3; base = 12 + (rem / 9) * 9; rem %= 9; a = rem / 3;  b = rem % 3; }
}

__global__ void k_pre1(const float* __restrict__ d1, const float* __restrict__ d2,
                       const float* __restrict__ d3, const float* __restrict__ bias) {
    for (int idx = threadIdx.x; idx < NS * NS; idx += blockDim.x) {
        int s = idx / NS, o = idx % NS;
        float v;
        if (o < 4)       v = d1[o * NS + s];
        else if (o < 12) { int rem = o - 4;  v = d2[((rem >> 2) * NS + s) * 4 + (rem & 3)]; }
        else             { int rem = o - 12; v = d3[((rem / 9) * NS + s) * 9 + (rem % 9)]; }
        g_fwd[s * NS + o] = v;
    }
    for (int j = threadIdx.x; j < KDIM; j += blockDim.x)
        g_biasx[j] = bias[j / NS];
}

__global__ void k_pre2() {  // U[s][t][(n,r,q)] = (d/48) sum_p fwd[s,(n,p,r)] fwd[t,(n,p,q)]
    __shared__ float sf[NS * NS];
    for (int i = threadIdx.x; i < NS * NS; i += blockDim.x) sf[i] = g_fwd[i];
    __syncthreads();
    int s = blockIdx.x;
    for (int e = threadIdx.x; e < NS * NS; e += blockDim.x) {
        int t = e / NS, o2 = e % NS;
        int d, base, r, q;
        decode_o(o2, d, base, r, q);
        float acc = 0.f;
        for (int p = 0; p < d; p++)
            acc += sf[s * NS + base + p * d + r] * sf[t * NS + base + p * d + q];
        g_U[(s * NS + t) * NS + o2] = acc * (float)d * (1.0f / 48.0f);
    }
}

__global__ void k_pre3(const float* __restrict__ kern) {  // kh[fc][o] = sum_s kern[fc,s] fwd[s,o]
    int fc = blockIdx.x;
    __shared__ float kr[NS];
    if (threadIdx.x < NS) kr[threadIdx.x] = kern[fc * NS + threadIdx.x];
    __syncthreads();
    if (threadIdx.x < NS) {
        float acc = 0.f;
        for (int s = 0; s < NS; s++) acc += kr[s] * g_fwd[s * NS + threadIdx.x];
        g_kh[fc * NS + threadIdx.x] = acc;
    }
}

// W[f*48+t][c*48+s] = sum_o2 kh[(f,c),o2] U[(s,t),o2]
// kh row register-resident; Us read as broadcast float4 LDS -> fma-pipe bound.
__global__ void k_pre4() {
    int s = blockIdx.x, f = blockIdx.y;
    __shared__ float4 Us4[NS * 12];
    for (int i = threadIdx.x; i < NS * NS; i += blockDim.x)
        ((float*)Us4)[i] = g_U[s * NS * NS + i];
    int c = threadIdx.x & 31;
    int t0 = threadIdx.x >> 5;      // 8 warps
    float kr[NS];
    const float* khp = g_kh + (size_t)(f * 32 + c) * NS;
#pragma unroll
    for (int o2 = 0; o2 < NS; o2++) kr[o2] = khp[o2];
    __syncthreads();
    for (int t = t0; t < NS; t += 8) {
        const float4* u = Us4 + t * 12;
        float acc = 0.f;
#pragma unroll
        for (int i = 0; i < 12; i++) {
            float4 v = u[i];
            acc += kr[4 * i] * v.x + kr[4 * i + 1] * v.y
                 + kr[4 * i + 2] * v.z + kr[4 * i + 3] * v.w;
        }
        g_W[(size_t)(f * NS + t) * KDIM + c * NS + s] = __float2half_rn(acc);
    }
}

// ---------------- main GEMM ------------------------------------------------
// 128x256 CTA tile, 8 warps (2x4) each 64x64, K staged 64 at a time, 3 stages.
// B (g_W, fp16) via cp.async; A (x, fp32) via LDG.128 -> cvt -> STS, pipelined
// 2 stages ahead so LDG latency hides under the mma block.

__device__ __forceinline__ void issue_B(int kt, int tid, unsigned sb,
                                        const __half* gw) {
    unsigned sa = sb + (unsigned)(kt % STAGES) * STAGE_BYTES + A_STG;
    const __half* gb = gw + kt * 64;
#pragma unroll
    for (int it = 0; it < 8; it++) {
        int j = tid + it * 256;                 // 0..2047 16B chunks
        int r = j >> 3, c = j & 7;
        unsigned soff = (unsigned)r * 128u + (unsigned)((c ^ (r & 7)) << 4);
        cpa16(sa + soff, gb + (size_t)r * KDIM + c * 8);
    }
}

__device__ __forceinline__ void ldg_A(int kt, int tid, const float* gx, float4* v) {
#pragma unroll
    for (int it = 0; it < 4; it++) {
        int j = tid + it * 256;                 // 0..1023 16B-fp16 chunks
        int r = j >> 3, c = j & 7;
        const float4* p = (const float4*)(gx + (size_t)r * KDIM + kt * 64 + c * 8);
        v[2 * it]     = p[0];
        v[2 * it + 1] = p[1];
    }
}

__device__ __forceinline__ void sts_A(int kt, int tid, char* smem, const float4* v) {
    char* sa = smem + (size_t)(kt % STAGES) * STAGE_BYTES;
#pragma unroll
    for (int it = 0; it < 4; it++) {
        int j = tid + it * 256;
        int r = j >> 3, c = j & 7;
        unsigned soff = (unsigned)r * 128u + (unsigned)((c ^ (r & 7)) << 4);
        float4 v0 = v[2 * it], v1 = v[2 * it + 1];
        __half2 h[4];
        h[0] = __floats2half2_rn(v0.x, v0.y);
        h[1] = __floats2half2_rn(v0.z, v0.w);
        h[2] = __floats2half2_rn(v1.x, v1.y);
        h[3] = __floats2half2_rn(v1.z, v1.w);
        *(uint4*)(sa + soff) = *(const uint4*)h;
    }
}

__global__ void __launch_bounds__(256, 1) k_gemm(float* __restrict__ out,
                                                 const float* __restrict__ x) {
    extern __shared__ char smem[];
    unsigned sb = s2u(smem);
    int tid = threadIdx.x, lane = tid & 31, wid = tid >> 5;
    int wm = wid & 1, wn = wid >> 1;
    int n0 = blockIdx.x * BN, m0 = blockIdx.y * BM;

    const float*  gx = x   + (size_t)m0 * KDIM;
    const __half* gw = g_W + (size_t)n0 * KDIM;

    float acc[4][8][4];
#pragma unroll
    for (int i = 0; i < 4; i++)
#pragma unroll
        for (int j = 0; j < 8; j++)
#pragma unroll
            for (int e = 0; e < 4; e++) acc[i][j][e] = 0.f;

    unsigned rowA = lane & 15;
    unsigned hkA  = lane >> 4;
    unsigned rowB = (lane & 7) | ((lane & 16) >> 1);
    unsigned ckB  = (lane >> 3) & 1;
    unsigned xorA = (lane & 7) << 4;

    float4 areg[8];
    // prologue: stages 0,1 (A synchronous; LDG stall here is once-off)
    ldg_A(0, tid, gx, areg); sts_A(0, tid, smem, areg);
    issue_B(0, tid, sb, gw); CPA_COMMIT;
    ldg_A(1, tid, gx, areg); sts_A(1, tid, smem, areg);
    issue_B(1, tid, sb, gw); CPA_COMMIT;

    for (int kt = 0; kt < KT; kt++) {
        bool pf = (kt + 2 < KT);
        if (pf) { ldg_A(kt + 2, tid, gx, areg); issue_B(kt + 2, tid, sb, gw); }
        CPA_COMMIT;
        CPA_WAIT2;
        __syncthreads();
        unsigned stg   = sb + (unsigned)(kt % STAGES) * STAGE_BYTES;
        unsigned baseA = stg + (unsigned)wm * (64 * 128) + rowA * 128;
        unsigned baseB = stg + A_STG + (unsigned)wn * (64 * 128) + rowB * 128;
#pragma unroll
        for (int s4 = 0; s4 < 4; s4++) {
            unsigned a[4][4], b[4][4];
            unsigned chA = (((2 * s4 + hkA) << 4) ^ xorA);
            unsigned chB = (((2 * s4 + ckB) << 4) ^ xorA);
#pragma unroll
            for (int mi = 0; mi < 4; mi++) ldsm4(a[mi], baseA + mi * 2048 + chA);
#pragma unroll
            for (int nj = 0; nj < 4; nj++) ldsm4(b[nj], baseB + nj * 2048 + chB);
#pragma unroll
            for (int mi = 0; mi < 4; mi++)
#pragma unroll
                for (int nj = 0; nj < 8; nj++)
                    mma16816(acc[mi][nj], a[mi],
                             b[nj >> 1][(nj & 1) * 2], b[nj >> 1][(nj & 1) * 2 + 1]);
        }
        if (pf) sts_A(kt + 2, tid, smem, areg);
        __syncthreads();
    }

    // ---- epilogue: direct float2 stores + bias ----
    int rbase = m0 + wm * 64 + (lane >> 2);
    int cbase = n0 + wn * 64 + 2 * (lane & 3);
#pragma unroll
    for (int nj = 0; nj < 8; nj++) {
        int col = cbase + nj * 8;
        float b0 = g_biasx[col], b1 = g_biasx[col + 1];
#pragma unroll
        for (int mi = 0; mi < 4; mi++) {
            int r0 = rbase + mi * 16;
            float2 v0 = make_float2(acc[mi][nj][0] + b0, acc[mi][nj][1] + b1);
            float2 v1 = make_float2(acc[mi][nj][2] + b0, acc[mi][nj][3] + b1);
            *(float2*)&out[(size_t)r0 * KDIM + col] = v0;
            *(float2*)&out[(size_t)(r0 + 8) * KDIM + col] = v1;
        }
    }
}

// ---------------- launch ----------------------------------------------------
extern "C" void kernel_launch(void* const* d_in, const int* in_sizes, int n_in,
                              void* d_out, int out_size) {
    const float* x    = (const float*)d_in[0];
    const float* kern = (const float*)d_in[1];
    const float* bias = (const float*)d_in[2];
    const float* d1   = (const float*)d_in[3];
    const float* d2   = (const float*)d_in[4];
    const float* d3   = (const float*)d_in[5];
    float* out = (float*)d_out;

    k_pre1<<<1, 256>>>(d1, d2, d3, bias);
    k_pre2<<<48, 256>>>();
    k_pre3<<<1024, 64>>>(kern);
    k_pre4<<<dim3(48, 32), 256>>>();

    cudaFuncSetAttribute(k_gemm, cudaFuncAttributeMaxDynamicSharedMemorySize, GEMM_SMEM);
    k_gemm<<<dim3(KDIM / BN, BDIM / BM), 256, GEMM_SMEM>>>(out, x);
}

// round 5
// speedup vs baseline: 1.1937x; 1.1030x over previous
#include <cuda_runtime.h>
#include <cuda_fp16.h>
#include <cstdint>

#define NS 48
#define BDIM 32768
#define KDIM 1536
#define KT 24              // K chunks of 64
#define STAGES 4
#define BM 128
#define BN 256
#define A_STG 16384        // 128 rows x 128B (fp16)
#define B_STG 32768        // 256 rows x 128B (fp16)
#define STAGE_BYTES (A_STG + B_STG)          // 49152
#define GEMM_SMEM (STAGES * STAGE_BYTES)     // 196608

// ---------------- device-global scratch (no runtime allocation allowed) ----
__device__ __half g_W[(size_t)KDIM * KDIM];     // fused operator [N=1536][K=1536], K contiguous
__device__ float  g_fwd[NS * NS];               // [s][o]
__device__ float  g_U[NS * NS * NS];            // [s][t][o2]
__device__ float  g_kh[32 * 32 * NS];           // [f*32+c][o2]
__device__ float  g_biasx[KDIM];                // bias broadcast over t

// ---------------- PTX helpers ---------------------------------------------
__device__ __forceinline__ unsigned s2u(const void* p) {
    return (unsigned)__cvta_generic_to_shared(p);
}
__device__ __forceinline__ void cpa16(unsigned s, const void* g) {
    asm volatile("cp.async.cg.shared.global [%0], [%1], 16;" :: "r"(s), "l"(g));
}
#define CPA_COMMIT asm volatile("cp.async.commit_group;" ::: "memory")
#define CPA_WAIT2  asm volatile("cp.async.wait_group 2;" ::: "memory")

__device__ __forceinline__ void ldsm4(unsigned* r, unsigned addr) {
    asm volatile("ldmatrix.sync.aligned.m8n8.x4.shared.b16 {%0,%1,%2,%3}, [%4];"
                 : "=r"(r[0]), "=r"(r[1]), "=r"(r[2]), "=r"(r[3]) : "r"(addr));
}
__device__ __forceinline__ void mma16816(float* d, const unsigned* a,
                                         unsigned b0, unsigned b1) {
    asm volatile(
        "mma.sync.aligned.m16n8k16.row.col.f32.f16.f16.f32 "
        "{%0,%1,%2,%3}, {%4,%5,%6,%7}, {%8,%9}, {%0,%1,%2,%3};"
        : "+f"(d[0]), "+f"(d[1]), "+f"(d[2]), "+f"(d[3])
        : "r"(a[0]), "r"(a[1]), "r"(a[2]), "r"(a[3]), "r"(b0), "r"(b1));
}

// ---------------- precompute -----------------------------------------------
__device__ __forceinline__ void decode_o(int o, int& d, int& base, int& a, int& b) {
    if (o < 4)       { d = 1; base = o; a = 0; b = 0; }
    else if (o < 12) { int rem = o - 4;  d = 2; base = 4 + (rem >> 2) * 4; rem &= 3;  a = rem >> 1; b = rem & 1; }
    else             { int rem = o - 12; d = 3; base = 12 + (rem / 9) * 9; rem %= 9; a = rem / 3;  b = rem % 3; }
}

__global__ void k_pre1(const float* __restrict__ d1, const float* __restrict__ d2,
                       const float* __restrict__ d3, const float* __restrict__ bias) {
    for (int idx = threadIdx.x; idx < NS * NS; idx += blockDim.x) {
        int s = idx / NS, o = idx % NS;
        float v;
        if (o < 4)       v = d1[o * NS + s];
        else if (o < 12) { int rem = o - 4;  v = d2[((rem >> 2) * NS + s) * 4 + (rem & 3)]; }
        else             { int rem = o - 12; v = d3[((rem / 9) * NS + s) * 9 + (rem % 9)]; }
        g_fwd[s * NS + o] = v;
    }
    for (int j = threadIdx.x; j < KDIM; j += blockDim.x)
        g_biasx[j] = bias[j / NS];
}

__global__ void k_pre2() {  // U[s][t][(n,r,q)] = (d/48) sum_p fwd[s,(n,p,r)] fwd[t,(n,p,q)]
    __shared__ float sf[NS * NS];
    for (int i = threadIdx.x; i < NS * NS; i += blockDim.x) sf[i] = g_fwd[i];
    __syncthreads();
    int s = blockIdx.x;
    for (int e = threadIdx.x; e < NS * NS; e += blockDim.x) {
        int t = e / NS, o2 = e % NS;
        int d, base, r, q;
        decode_o(o2, d, base, r, q);
        float acc = 0.f;
        for (int p = 0; p < d; p++)
            acc += sf[s * NS + base + p * d + r] * sf[t * NS + base + p * d + q];
        g_U[(s * NS + t) * NS + o2] = acc * (float)d * (1.0f / 48.0f);
    }
}

__global__ void k_pre3(const float* __restrict__ kern) {  // kh[fc][o] = sum_s kern[fc,s] fwd[s,o]
    int fc = blockIdx.x;
    __shared__ float kr[NS];
    if (threadIdx.x < NS) kr[threadIdx.x] = kern[fc * NS + threadIdx.x];
    __syncthreads();
    if (threadIdx.x < NS) {
        float acc = 0.f;
        for (int s = 0; s < NS; s++) acc += kr[s] * g_fwd[s * NS + threadIdx.x];
        g_kh[fc * NS + threadIdx.x] = acc;
    }
}

// W[f*48+t][c*48+s] = sum_o2 kh[(f,c),o2] U[(s,t),o2]
// kh staged coalesced into smem (rows padded to 49 -> conflict-free register
// fill), U read as broadcast float4 LDS -> FFMA-bound.
__global__ void k_pre4() {
    int s = blockIdx.x, f = blockIdx.y;
    __shared__ float Us[NS * NS];        // [t][o2]
    __shared__ float khs[32 * (NS + 1)]; // [c][o2], padded
    for (int i = threadIdx.x; i < NS * NS; i += 256) Us[i] = g_U[s * NS * NS + i];
    for (int i = threadIdx.x; i < 32 * NS; i += 256)
        khs[(i / NS) * (NS + 1) + (i % NS)] = g_kh[(size_t)(f * 32) * NS + i];
    __syncthreads();
    int c = threadIdx.x & 31, t0 = threadIdx.x >> 5;
    float kr[NS];
#pragma unroll
    for (int o2 = 0; o2 < NS; o2++) kr[o2] = khs[c * (NS + 1) + o2];
    for (int t = t0; t < NS; t += 8) {
        const float4* u = (const float4*)(Us + t * NS);
        float acc = 0.f;
#pragma unroll
        for (int i = 0; i < 12; i++) {
            float4 v = u[i];
            acc += kr[4 * i] * v.x + kr[4 * i + 1] * v.y
                 + kr[4 * i + 2] * v.z + kr[4 * i + 3] * v.w;
        }
        g_W[(size_t)(f * NS + t) * KDIM + c * NS + s] = __float2half_rn(acc);
    }
}

// ---------------- main GEMM ------------------------------------------------
// 128x256 CTA tile, 8 warps (2x4) each 64x64, K staged 64 at a time, 4 stages.
// B (g_W, fp16) via cp.async; A (x, fp32) via LDG.128 -> cvt -> STS, pipelined
// 2 stages ahead. Single __syncthreads per K-iter (4 stages make the trailing
// barrier unnecessary: writes target (kt+2)%4/(kt+3)%4, reads kt%4).

__device__ __forceinline__ void issue_B(int kt, int tid, unsigned sb,
                                        const __half* gw) {
    unsigned sa = sb + (unsigned)(kt % STAGES) * STAGE_BYTES + A_STG;
    const __half* gb = gw + kt * 64;
#pragma unroll
    for (int it = 0; it < 8; it++) {
        int j = tid + it * 256;                 // 0..2047 16B chunks
        int r = j >> 3, c = j & 7;
        unsigned soff = (unsigned)r * 128u + (unsigned)((c ^ (r & 7)) << 4);
        cpa16(sa + soff, gb + (size_t)r * KDIM + c * 8);
    }
}

__device__ __forceinline__ void ldg_A(int kt, int tid, const float* gx, float4* v) {
#pragma unroll
    for (int it = 0; it < 4; it++) {
        int j = tid + it * 256;                 // 0..1023 16B-fp16 chunks
        int r = j >> 3, c = j & 7;
        const float4* p = (const float4*)(gx + (size_t)r * KDIM + kt * 64 + c * 8);
        v[2 * it]     = p[0];
        v[2 * it + 1] = p[1];
    }
}

__device__ __forceinline__ void sts_A(int kt, int tid, char* smem, const float4* v) {
    char* sa = smem + (size_t)(kt % STAGES) * STAGE_BYTES;
#pragma unroll
    for (int it = 0; it < 4; it++) {
        int j = tid + it * 256;
        int r = j >> 3, c = j & 7;
        unsigned soff = (unsigned)r * 128u + (unsigned)((c ^ (r & 7)) << 4);
        float4 v0 = v[2 * it], v1 = v[2 * it + 1];
        __half2 h[4];
        h[0] = __floats2half2_rn(v0.x, v0.y);
        h[1] = __floats2half2_rn(v0.z, v0.w);
        h[2] = __floats2half2_rn(v1.x, v1.y);
        h[3] = __floats2half2_rn(v1.z, v1.w);
        *(uint4*)(sa + soff) = *(const uint4*)h;
    }
}

__global__ void __launch_bounds__(256, 1) k_gemm(float* __restrict__ out,
                                                 const float* __restrict__ x) {
    extern __shared__ char smem[];
    unsigned sb = s2u(smem);
    int tid = threadIdx.x, lane = tid & 31, wid = tid >> 5;
    int wm = wid & 1, wn = wid >> 1;
    int n0 = blockIdx.x * BN, m0 = blockIdx.y * BM;

    const float*  gx = x   + (size_t)m0 * KDIM;
    const __half* gw = g_W + (size_t)n0 * KDIM;

    float acc[4][8][4];
#pragma unroll
    for (int i = 0; i < 4; i++)
#pragma unroll
        for (int j = 0; j < 8; j++)
#pragma unroll
            for (int e = 0; e < 4; e++) acc[i][j][e] = 0.f;

    unsigned rowA = lane & 15;
    unsigned hkA  = lane >> 4;
    unsigned rowB = (lane & 7) | ((lane & 16) >> 1);
    unsigned ckB  = (lane >> 3) & 1;
    unsigned xorA = (lane & 7) << 4;

    float4 areg[8];
    // prologue: stages 0,1 (A synchronous; LDG stall here is once-off)
    ldg_A(0, tid, gx, areg); sts_A(0, tid, smem, areg);
    issue_B(0, tid, sb, gw); CPA_COMMIT;
    ldg_A(1, tid, gx, areg); sts_A(1, tid, smem, areg);
    issue_B(1, tid, sb, gw); CPA_COMMIT;

    for (int kt = 0; kt < KT; kt++) {
        bool pf = (kt + 2 < KT);
        if (pf) { ldg_A(kt + 2, tid, gx, areg); issue_B(kt + 2, tid, sb, gw); }
        CPA_COMMIT;
        CPA_WAIT2;
        __syncthreads();
        unsigned stg   = sb + (unsigned)(kt % STAGES) * STAGE_BYTES;
        unsigned baseA = stg + (unsigned)wm * (64 * 128) + rowA * 128;
        unsigned baseB = stg + A_STG + (unsigned)wn * (64 * 128) + rowB * 128;
#pragma unroll
        for (int s4 = 0; s4 < 4; s4++) {
            unsigned a[4][4], b[4][4];
            unsigned chA = (((2 * s4 + hkA) << 4) ^ xorA);
            unsigned chB = (((2 * s4 + ckB) << 4) ^ xorA);
#pragma unroll
            for (int mi = 0; mi < 4; mi++) ldsm4(a[mi], baseA + mi * 2048 + chA);
#pragma unroll
            for (int nj = 0; nj < 4; nj++) ldsm4(b[nj], baseB + nj * 2048 + chB);
#pragma unroll
            for (int mi = 0; mi < 4; mi++)
#pragma unroll
                for (int nj = 0; nj < 8; nj++)
                    mma16816(acc[mi][nj], a[mi],
                             b[nj >> 1][(nj & 1) * 2], b[nj >> 1][(nj & 1) * 2 + 1]);
        }
        if (pf) sts_A(kt + 2, tid, smem, areg);
    }

    // ---- epilogue: direct float2 stores + bias ----
    int rbase = m0 + wm * 64 + (lane >> 2);
    int cbase = n0 + wn * 64 + 2 * (lane & 3);
#pragma unroll
    for (int nj = 0; nj < 8; nj++) {
        int col = cbase + nj * 8;
        float b0 = g_biasx[col], b1 = g_biasx[col + 1];
#pragma unroll
        for (int mi = 0; mi < 4; mi++) {
            int r0 = rbase + mi * 16;
            float2 v0 = make_float2(acc[mi][nj][0] + b0, acc[mi][nj][1] + b1);
            float2 v1 = make_float2(acc[mi][nj][2] + b0, acc[mi][nj][3] + b1);
            *(float2*)&out[(size_t)r0 * KDIM + col] = v0;
            *(float2*)&out[(size_t)(r0 + 8) * KDIM + col] = v1;
        }
    }
}

// ---------------- launch ----------------------------------------------------
extern "C" void kernel_launch(void* const* d_in, const int* in_sizes, int n_in,
                              void* d_out, int out_size) {
    const float* x    = (const float*)d_in[0];
    const float* kern = (const float*)d_in[1];
    const float* bias = (const float*)d_in[2];
    const float* d1   = (const float*)d_in[3];
    const float* d2   = (const float*)d_in[4];
    const float* d3   = (const float*)d_in[5];
    float* out = (float*)d_out;

    k_pre1<<<1, 256>>>(d1, d2, d3, bias);
    k_pre2<<<48, 256>>>();
    k_pre3<<<1024, 64>>>(kern);
    k_pre4<<<dim3(48, 32), 256>>>();

    cudaFuncSetAttribute(k_gemm, cudaFuncAttributeMaxDynamicSharedMemorySize, GEMM_SMEM);
    k_gemm<<<dim3(KDIM / BN, BDIM / BM), 256, GEMM_SMEM>>>(out, x);
}